// round 2
// baseline (speedup 1.0000x reference)
#include <cuda_runtime.h>

// Problem constants (fixed shapes)
#define BB 8
#define GG 64
#define CC 192
#define HH 256
#define WW 256
#define HWN 65536          // H*W
#define OO 256             // width2

// Scratch: per (b,g): {A0, A1, A2, C} where A_j = bn1_scale[g]*softmax_j,
// C = bn1_beta[g] - bn1_scale[g]*bn1_mean[g]
__device__ float4 g_attnW[BB * GG];
// Duplicated transposed conv weight: g_Wd[k][2*o + {0,1}] = convw[o][k]
// Layout per k-row: 512 floats = 128 float4; float4 = {w_o, w_o, w_{o+1}, w_{o+1}}
__device__ __align__(16) float g_Wd[64 * 512];
// Precomputed bn2 affine: {scale, bias} per output channel
__device__ float2 g_bn2[OO];

union F2U { float2 f; unsigned long long u; };

__device__ __forceinline__ float2 ffma2(float2 a, float2 b, float2 c) {
    F2U A, B, C, D;
    A.f = a; B.f = b; C.f = c;
    asm("fma.rn.f32x2 %0, %1, %2, %3;" : "=l"(D.u) : "l"(A.u), "l"(B.u), "l"(C.u));
    return D.f;
}

// ---------------------------------------------------------------------------
// Kernel 0: prep — duplicate/transpose conv_w, fold bn2.
// ---------------------------------------------------------------------------
__global__ __launch_bounds__(256) void prep_kernel(
    const float* __restrict__ convw,   // (O, G) row-major
    const float* __restrict__ bn2_g, const float* __restrict__ bn2_b,
    const float* __restrict__ bn2_m, const float* __restrict__ bn2_v)
{
    const int i = blockIdx.x * 256 + threadIdx.x;   // 0..16383
    const int k = i & 63;
    const int o = i >> 6;
    float w = convw[o * GG + k];
    ((float2*)g_Wd)[k * 256 + o] = make_float2(w, w);
    if (i < OO) {
        float sc = bn2_g[i] * rsqrtf(bn2_v[i] + 1e-5f);
        float bi = bn2_b[i] - sc * bn2_m[i];
        g_bn2[i] = make_float2(sc, bi);
    }
}

// ---------------------------------------------------------------------------
// Kernel 1: attention statistics (unchanged from R1 — HBM-bound, ~62us).
// ---------------------------------------------------------------------------
__global__ __launch_bounds__(256) void attn_kernel(
    const float* __restrict__ x,
    const float* __restrict__ aw,      // (G,3)
    const float* __restrict__ bn1_g, const float* __restrict__ bn1_b,
    const float* __restrict__ bn1_m, const float* __restrict__ bn1_v)
{
    const int bg = blockIdx.x;             // b*G + g
    const int g  = bg & 63;
    const float* xb = x + (size_t)bg * 3 * HWN;

    const int t    = threadIdx.x;
    const int lane = t & 31;
    const int warp = t >> 5;

    float acc[9];
#pragma unroll
    for (int q = 0; q < 9; q++) acc[q] = 0.0f;

#pragma unroll 1
    for (int it = 0; it < 16; it++) {
        const int wIdx = it * 256 + t;
        const int wy = wIdx >> 6;
        const int wx = wIdx & 63;
        float m[3], s[3];
#pragma unroll
        for (int ch = 0; ch < 3; ch++) {
            const float4* pc = (const float4*)(xb + (size_t)ch * HWN + (wy * 4) * WW + wx * 4);
            float4 r0 = __ldcs(pc);
            float4 r1 = __ldcs(pc + (WW / 4));
            float4 r2 = __ldcs(pc + 2 * (WW / 4));
            float4 r3 = __ldcs(pc + 3 * (WW / 4));
            float mx = fmaxf(fmaxf(fmaxf(r0.x, r0.y), fmaxf(r0.z, r0.w)),
                      fmaxf(fmaxf(fmaxf(r1.x, r1.y), fmaxf(r1.z, r1.w)),
                      fmaxf(fmaxf(fmaxf(r2.x, r2.y), fmaxf(r2.z, r2.w)),
                            fmaxf(fmaxf(r3.x, r3.y), fmaxf(r3.z, r3.w)))));
            float sm = (r0.x + r0.y + r0.z + r0.w) + (r1.x + r1.y + r1.z + r1.w)
                     + (r2.x + r2.y + r2.z + r2.w) + (r3.x + r3.y + r3.z + r3.w);
            m[ch] = mx;
            s[ch] = sm;
        }
#pragma unroll
        for (int i = 0; i < 3; i++)
#pragma unroll
            for (int j = 0; j < 3; j++)
                acc[i * 3 + j] += m[i] * s[j];
    }

    __shared__ float red[9][8];
    __shared__ float fin[9];
#pragma unroll
    for (int q = 0; q < 9; q++) {
        float v = acc[q];
#pragma unroll
        for (int off = 16; off > 0; off >>= 1)
            v += __shfl_xor_sync(0xFFFFFFFFu, v, off);
        if (lane == 0) red[q][warp] = v;
    }
    __syncthreads();
    if (t < 9) {
        float s = 0.0f;
#pragma unroll
        for (int w = 0; w < 8; w++) s += red[t][w];
        fin[t] = s;
    }
    __syncthreads();

    if (t == 0) {
        const float w0 = aw[g * 3 + 0], w1 = aw[g * 3 + 1], w2 = aw[g * 3 + 2];
        float r0 = (fin[0] * w0 + fin[3] * w1 + fin[6] * w2) * (1.0f / 1024.0f);
        float r1 = (fin[1] * w0 + fin[4] * w1 + fin[7] * w2) * (1.0f / 1024.0f);
        float r2 = (fin[2] * w0 + fin[5] * w1 + fin[8] * w2) * (1.0f / 1024.0f);
        float mx = fmaxf(r0, fmaxf(r1, r2));
        float e0 = __expf(r0 - mx), e1 = __expf(r1 - mx), e2 = __expf(r2 - mx);
        float inv = 1.0f / (e0 + e1 + e2);
        float sc = bn1_g[g] * rsqrtf(bn1_v[g] + 1e-5f);
        float cc = bn1_b[g] - sc * bn1_m[g];
        float4 o;
        o.x = sc * e0 * inv;
        o.y = sc * e1 * inv;
        o.z = sc * e2 * inv;
        o.w = cc;
        g_attnW[bg] = o;
    }
}

// ---------------------------------------------------------------------------
// Kernel 2: fused weighted-sum + bn1 + relu + 1x1 conv (FFMA2) + bn2.
// 256 threads, 2 CTAs/SM. Block tile: 256 outputs x 64 positions.
// Phase A: ygr[k=64][n=64] in smem. Phase B: K=64 GEMM with packed f32x2 FMA,
// micro-tile 8o x 8n (acc = 32 f32x2), W duplicated pairs via L1 (__ldg).
// ---------------------------------------------------------------------------
__global__ __launch_bounds__(256, 2) void fused_kernel(
    const float* __restrict__ x,
    float* __restrict__ out)
{
    __shared__ __align__(16) float ygr[64 * 64];

    const int b  = blockIdx.y;
    const int n0 = blockIdx.x * 64;
    const int t  = threadIdx.x;

    // ---- Phase A ----
    {
        const int pos = t & 63;
        const int gq  = t >> 6;                       // 0..3
        const float* xb = x + (size_t)b * CC * HWN + n0 + pos;
        const float4* awb = g_attnW + b * GG;
#pragma unroll
        for (int it = 0; it < 16; it++) {
            const int g = it * 4 + gq;
            const float4 a = __ldg(awb + g);
            const float* p = xb + (size_t)(g * 3) * HWN;
            float x0 = __ldcs(p);
            float x1 = __ldcs(p + HWN);
            float x2 = __ldcs(p + 2 * HWN);
            float y = fmaf(a.x, x0, fmaf(a.y, x1, fmaf(a.z, x2, a.w)));
            ygr[g * 64 + pos] = fmaxf(y, 0.0f);
        }
    }
    __syncthreads();

    // ---- Phase B: FFMA2 GEMM ----
    const int nt = t & 7;         // 8 n-groups of 8
    const int ot = t >> 3;        // 32 o-groups of 8
    const int nn = nt * 8;
    const int oo = ot * 8;

    float2 acc[8][4];             // [o][n-pair]
#pragma unroll
    for (int i = 0; i < 8; i++)
#pragma unroll
        for (int jp = 0; jp < 4; jp++) acc[i][jp] = make_float2(0.0f, 0.0f);

    const float4* wdp = (const float4*)g_Wd + (oo >> 1);  // + ot*4

#pragma unroll 4
    for (int k = 0; k < 64; k++) {
        // {w_o,w_o,w_{o+1},w_{o+1}} quads for 8 o's
        float4 w01 = __ldg(wdp + k * 128 + 0);
        float4 w23 = __ldg(wdp + k * 128 + 1);
        float4 w45 = __ldg(wdp + k * 128 + 2);
        float4 w67 = __ldg(wdp + k * 128 + 3);
        float4 y03 = *(const float4*)&ygr[k * 64 + nn];
        float4 y47 = *(const float4*)&ygr[k * 64 + nn + 4];

        float2 wp[8];
        wp[0] = make_float2(w01.x, w01.y); wp[1] = make_float2(w01.z, w01.w);
        wp[2] = make_float2(w23.x, w23.y); wp[3] = make_float2(w23.z, w23.w);
        wp[4] = make_float2(w45.x, w45.y); wp[5] = make_float2(w45.z, w45.w);
        wp[6] = make_float2(w67.x, w67.y); wp[7] = make_float2(w67.z, w67.w);
        float2 yp[4];
        yp[0] = make_float2(y03.x, y03.y); yp[1] = make_float2(y03.z, y03.w);
        yp[2] = make_float2(y47.x, y47.y); yp[3] = make_float2(y47.z, y47.w);

#pragma unroll
        for (int i = 0; i < 8; i++)
#pragma unroll
            for (int jp = 0; jp < 4; jp++)
                acc[i][jp] = ffma2(wp[i], yp[jp], acc[i][jp]);
    }

    // ---- Epilogue: bn2 (precomputed) + store ----
    float* ob = out + (size_t)b * OO * HWN + n0 + nn;
#pragma unroll
    for (int i = 0; i < 8; i++) {
        const int o = oo + i;
        const float2 sb = g_bn2[o];
        float4 v0, v1;
        v0.x = fmaf(acc[i][0].x, sb.x, sb.y);
        v0.y = fmaf(acc[i][0].y, sb.x, sb.y);
        v0.z = fmaf(acc[i][1].x, sb.x, sb.y);
        v0.w = fmaf(acc[i][1].y, sb.x, sb.y);
        v1.x = fmaf(acc[i][2].x, sb.x, sb.y);
        v1.y = fmaf(acc[i][2].y, sb.x, sb.y);
        v1.z = fmaf(acc[i][3].x, sb.x, sb.y);
        v1.w = fmaf(acc[i][3].y, sb.x, sb.y);
        float* po = ob + (size_t)o * HWN;
        *(float4*)po = v0;
        *(float4*)(po + 4) = v1;
    }
}

extern "C" void kernel_launch(void* const* d_in, const int* in_sizes, int n_in,
                              void* d_out, int out_size)
{
    const float* x     = (const float*)d_in[0];
    const float* aw    = (const float*)d_in[1];
    const float* bn1_g = (const float*)d_in[2];
    const float* bn1_b = (const float*)d_in[3];
    const float* bn1_m = (const float*)d_in[4];
    const float* bn1_v = (const float*)d_in[5];
    const float* convw = (const float*)d_in[6];
    const float* bn2_g = (const float*)d_in[7];
    const float* bn2_b = (const float*)d_in[8];
    const float* bn2_m = (const float*)d_in[9];
    const float* bn2_v = (const float*)d_in[10];
    float* out = (float*)d_out;

    prep_kernel<<<64, 256>>>(convw, bn2_g, bn2_b, bn2_m, bn2_v);
    attn_kernel<<<BB * GG, 256>>>(x, aw, bn1_g, bn1_b, bn1_m, bn1_v);
    fused_kernel<<<dim3(HWN / 64, BB), 256>>>(x, out);
}

// round 3
// speedup vs baseline: 1.0055x; 1.0055x over previous
#include <cuda_runtime.h>

// Problem constants (fixed shapes)
#define BB 8
#define GG 64
#define CC 192
#define HH 256
#define WW 256
#define HWN 65536          // H*W
#define OO 256             // width2

typedef unsigned long long u64;

// Scratch: per (b,g): {A0, A1, A2, C} where A_j = bn1_scale[g]*softmax_j,
// C = bn1_beta[g] - bn1_scale[g]*bn1_mean[g]
__device__ float4 g_attnW[BB * GG];
// Duplicated transposed conv weight, u64-packed: pair[k*256 + o] = {w_ok, w_ok}
__device__ __align__(16) u64 g_Wd[64 * 256];
// Precomputed bn2 affine: {scale, bias} per output channel
__device__ float2 g_bn2[OO];

union U64F2 { u64 u; float2 f; };

__device__ __forceinline__ u64 ffma2(u64 a, u64 b, u64 c) {
    u64 d;
    asm("fma.rn.f32x2 %0, %1, %2, %3;" : "=l"(d) : "l"(a), "l"(b), "l"(c));
    return d;
}

// ---------------------------------------------------------------------------
// Kernel 0: prep — duplicate/transpose conv_w, fold bn2.
// ---------------------------------------------------------------------------
__global__ __launch_bounds__(256) void prep_kernel(
    const float* __restrict__ convw,   // (O, G) row-major
    const float* __restrict__ bn2_g, const float* __restrict__ bn2_b,
    const float* __restrict__ bn2_m, const float* __restrict__ bn2_v)
{
    const int i = blockIdx.x * 256 + threadIdx.x;   // 0..16383
    const int k = i & 63;
    const int o = i >> 6;
    float w = convw[o * GG + k];
    U64F2 p; p.f = make_float2(w, w);
    g_Wd[k * 256 + o] = p.u;
    if (i < OO) {
        float sc = bn2_g[i] * rsqrtf(bn2_v[i] + 1e-5f);
        float bi = bn2_b[i] - sc * bn2_m[i];
        g_bn2[i] = make_float2(sc, bi);
    }
}

// ---------------------------------------------------------------------------
// Kernel 1: attention statistics (HBM-bound, ~62us).
// ---------------------------------------------------------------------------
__global__ __launch_bounds__(256) void attn_kernel(
    const float* __restrict__ x,
    const float* __restrict__ aw,      // (G,3)
    const float* __restrict__ bn1_g, const float* __restrict__ bn1_b,
    const float* __restrict__ bn1_m, const float* __restrict__ bn1_v)
{
    const int bg = blockIdx.x;             // b*G + g
    const int g  = bg & 63;
    const float* xb = x + (size_t)bg * 3 * HWN;

    const int t    = threadIdx.x;
    const int lane = t & 31;
    const int warp = t >> 5;

    float acc[9];
#pragma unroll
    for (int q = 0; q < 9; q++) acc[q] = 0.0f;

#pragma unroll 1
    for (int it = 0; it < 16; it++) {
        const int wIdx = it * 256 + t;
        const int wy = wIdx >> 6;
        const int wx = wIdx & 63;
        float m[3], s[3];
#pragma unroll
        for (int ch = 0; ch < 3; ch++) {
            const float4* pc = (const float4*)(xb + (size_t)ch * HWN + (wy * 4) * WW + wx * 4);
            float4 r0 = __ldcs(pc);
            float4 r1 = __ldcs(pc + (WW / 4));
            float4 r2 = __ldcs(pc + 2 * (WW / 4));
            float4 r3 = __ldcs(pc + 3 * (WW / 4));
            float mx = fmaxf(fmaxf(fmaxf(r0.x, r0.y), fmaxf(r0.z, r0.w)),
                      fmaxf(fmaxf(fmaxf(r1.x, r1.y), fmaxf(r1.z, r1.w)),
                      fmaxf(fmaxf(fmaxf(r2.x, r2.y), fmaxf(r2.z, r2.w)),
                            fmaxf(fmaxf(r3.x, r3.y), fmaxf(r3.z, r3.w)))));
            float sm = (r0.x + r0.y + r0.z + r0.w) + (r1.x + r1.y + r1.z + r1.w)
                     + (r2.x + r2.y + r2.z + r2.w) + (r3.x + r3.y + r3.z + r3.w);
            m[ch] = mx;
            s[ch] = sm;
        }
#pragma unroll
        for (int i = 0; i < 3; i++)
#pragma unroll
            for (int j = 0; j < 3; j++)
                acc[i * 3 + j] += m[i] * s[j];
    }

    __shared__ float red[9][8];
    __shared__ float fin[9];
#pragma unroll
    for (int q = 0; q < 9; q++) {
        float v = acc[q];
#pragma unroll
        for (int off = 16; off > 0; off >>= 1)
            v += __shfl_xor_sync(0xFFFFFFFFu, v, off);
        if (lane == 0) red[q][warp] = v;
    }
    __syncthreads();
    if (t < 9) {
        float s = 0.0f;
#pragma unroll
        for (int w = 0; w < 8; w++) s += red[t][w];
        fin[t] = s;
    }
    __syncthreads();

    if (t == 0) {
        const float w0 = aw[g * 3 + 0], w1 = aw[g * 3 + 1], w2 = aw[g * 3 + 2];
        float r0 = (fin[0] * w0 + fin[3] * w1 + fin[6] * w2) * (1.0f / 1024.0f);
        float r1 = (fin[1] * w0 + fin[4] * w1 + fin[7] * w2) * (1.0f / 1024.0f);
        float r2 = (fin[2] * w0 + fin[5] * w1 + fin[8] * w2) * (1.0f / 1024.0f);
        float mx = fmaxf(r0, fmaxf(r1, r2));
        float e0 = __expf(r0 - mx), e1 = __expf(r1 - mx), e2 = __expf(r2 - mx);
        float inv = 1.0f / (e0 + e1 + e2);
        float sc = bn1_g[g] * rsqrtf(bn1_v[g] + 1e-5f);
        float cc = bn1_b[g] - sc * bn1_m[g];
        float4 o;
        o.x = sc * e0 * inv;
        o.y = sc * e1 * inv;
        o.z = sc * e2 * inv;
        o.w = cc;
        g_attnW[bg] = o;
    }
}

// ---------------------------------------------------------------------------
// Kernel 2: fused weighted-sum + bn1 + relu + 1x1 conv (u64-native FFMA2) + bn2.
// 256 threads, 2 CTAs/SM. Block tile: 256 outputs x 64 positions.
// Phase A: ygr[k=64][n=64] in smem. Phase B: K=64 GEMM in packed f32x2:
// micro-tile 8o x 8n = 32 u64 accumulators; per k: 4 LDG.128 (pre-duplicated W
// pairs) + 2 LDS.128 (y pairs) + 32 FFMA2, no pack/unpack MOVs in the loop.
// ---------------------------------------------------------------------------
__global__ __launch_bounds__(256, 2) void fused_kernel(
    const float* __restrict__ x,
    float* __restrict__ out)
{
    __shared__ __align__(16) float ygr[64 * 64];

    const int b  = blockIdx.y;
    const int n0 = blockIdx.x * 64;
    const int t  = threadIdx.x;

    // ---- Phase A ----
    {
        const int pos = t & 63;
        const int gq  = t >> 6;                       // 0..3
        const float* xb = x + (size_t)b * CC * HWN + n0 + pos;
        const float4* awb = g_attnW + b * GG;
#pragma unroll
        for (int it = 0; it < 16; it++) {
            const int g = it * 4 + gq;
            const float4 a = __ldg(awb + g);
            const float* p = xb + (size_t)(g * 3) * HWN;
            float x0 = __ldcs(p);
            float x1 = __ldcs(p + HWN);
            float x2 = __ldcs(p + 2 * HWN);
            float y = fmaf(a.x, x0, fmaf(a.y, x1, fmaf(a.z, x2, a.w)));
            ygr[g * 64 + pos] = fmaxf(y, 0.0f);
        }
    }
    __syncthreads();

    // ---- Phase B: FFMA2 GEMM (u64-native) ----
    const int nt = t & 7;         // 8 n-groups of 8
    const int ot = t >> 3;        // 32 o-groups of 8
    const int nn = nt * 8;
    const int oo = ot * 8;

    u64 acc[8][4];                // [o][n-pair]
#pragma unroll
    for (int i = 0; i < 8; i++)
#pragma unroll
        for (int jp = 0; jp < 4; jp++) acc[i][jp] = 0ULL;

    // W pairs for this thread's 8 o's: g_Wd[k*256 + oo .. oo+7] = 4x ulonglong2
    const ulonglong2* wdp = (const ulonglong2*)g_Wd + (oo >> 1);   // + ot*4
    const ulonglong2* yrow = (const ulonglong2*)&ygr[nn];          // + k*(64/4? no: stride below)

#pragma unroll 4
    for (int k = 0; k < 64; k++) {
        ulonglong2 w01 = __ldg(wdp + (size_t)k * 128 + 0);
        ulonglong2 w23 = __ldg(wdp + (size_t)k * 128 + 1);
        ulonglong2 w45 = __ldg(wdp + (size_t)k * 128 + 2);
        ulonglong2 w67 = __ldg(wdp + (size_t)k * 128 + 3);
        // ygr row k, floats nn..nn+7 = 2x ulonglong2 (row stride 64 floats = 16 ull2)
        ulonglong2 ya = yrow[(size_t)k * 16 + 0];
        ulonglong2 yb = yrow[(size_t)k * 16 + 1];

#pragma unroll
        for (int i = 0; i < 8; i++) {
            u64 w = (i == 0) ? w01.x : (i == 1) ? w01.y : (i == 2) ? w23.x : (i == 3) ? w23.y
                  : (i == 4) ? w45.x : (i == 5) ? w45.y : (i == 6) ? w67.x : w67.y;
            acc[i][0] = ffma2(w, ya.x, acc[i][0]);
            acc[i][1] = ffma2(w, ya.y, acc[i][1]);
            acc[i][2] = ffma2(w, yb.x, acc[i][2]);
            acc[i][3] = ffma2(w, yb.y, acc[i][3]);
        }
    }

    // ---- Epilogue: bn2 (precomputed) + store ----
    float* ob = out + (size_t)b * OO * HWN + n0 + nn;
#pragma unroll
    for (int i = 0; i < 8; i++) {
        const int o = oo + i;
        const float2 sb = g_bn2[o];
        U64F2 a0, a1, a2, a3;
        a0.u = acc[i][0]; a1.u = acc[i][1]; a2.u = acc[i][2]; a3.u = acc[i][3];
        float4 v0, v1;
        v0.x = fmaf(a0.f.x, sb.x, sb.y);
        v0.y = fmaf(a0.f.y, sb.x, sb.y);
        v0.z = fmaf(a1.f.x, sb.x, sb.y);
        v0.w = fmaf(a1.f.y, sb.x, sb.y);
        v1.x = fmaf(a2.f.x, sb.x, sb.y);
        v1.y = fmaf(a2.f.y, sb.x, sb.y);
        v1.z = fmaf(a3.f.x, sb.x, sb.y);
        v1.w = fmaf(a3.f.y, sb.x, sb.y);
        float* po = ob + (size_t)o * HWN;
        *(float4*)po = v0;
        *(float4*)(po + 4) = v1;
    }
}

extern "C" void kernel_launch(void* const* d_in, const int* in_sizes, int n_in,
                              void* d_out, int out_size)
{
    const float* x     = (const float*)d_in[0];
    const float* aw    = (const float*)d_in[1];
    const float* bn1_g = (const float*)d_in[2];
    const float* bn1_b = (const float*)d_in[3];
    const float* bn1_m = (const float*)d_in[4];
    const float* bn1_v = (const float*)d_in[5];
    const float* convw = (const float*)d_in[6];
    const float* bn2_g = (const float*)d_in[7];
    const float* bn2_b = (const float*)d_in[8];
    const float* bn2_m = (const float*)d_in[9];
    const float* bn2_v = (const float*)d_in[10];
    float* out = (float*)d_out;

    prep_kernel<<<64, 256>>>(convw, bn2_g, bn2_b, bn2_m, bn2_v);
    attn_kernel<<<BB * GG, 256>>>(x, aw, bn1_g, bn1_b, bn1_m, bn1_v);
    fused_kernel<<<dim3(HWN / 64, BB), 256>>>(x, out);
}

// round 5
// speedup vs baseline: 3.9432x; 3.9216x over previous
#include <cuda_runtime.h>
#include <cuda_fp16.h>
#include <cstdint>

// Problem constants (fixed shapes)
#define BB 8
#define GG 64
#define CC 192
#define HWN 65536          // H*W
#define OO 256             // width2

#define WPITCH 72          // fp16 elements per row (144B): conflict-free ldmatrix

// ---------------------------------------------------------------------------
// Device scratch
// ---------------------------------------------------------------------------
// per (b,g): {A0,A1,A2,C}: A_j = bn1_scale*softmax_j, C = bn1 bias fold
__device__ float4 g_attnW[BB * GG];
// conv_w as fp16, [o][k] row-major with 72-elem pitch
__device__ __align__(16) __half g_Whalf[OO * WPITCH];
// bn2 affine {scale, bias}
__device__ float2 g_bn2[OO];

__device__ __forceinline__ uint32_t smem_u32(const void* p) {
    uint32_t a;
    asm("{ .reg .u64 t; cvta.to.shared.u64 t, %1; cvt.u32.u64 %0, t; }" : "=r"(a) : "l"(p));
    return a;
}

__device__ __forceinline__ void ldmat_x4(uint32_t* r, uint32_t addr) {
    asm volatile("ldmatrix.sync.aligned.m8n8.x4.shared.b16 {%0,%1,%2,%3}, [%4];"
                 : "=r"(r[0]), "=r"(r[1]), "=r"(r[2]), "=r"(r[3]) : "r"(addr));
}
__device__ __forceinline__ void ldmat_x2(uint32_t* r, uint32_t addr) {
    asm volatile("ldmatrix.sync.aligned.m8n8.x2.shared.b16 {%0,%1}, [%2];"
                 : "=r"(r[0]), "=r"(r[1]) : "r"(addr));
}
__device__ __forceinline__ void mma_16816(float* d, const uint32_t* a, const uint32_t* b) {
    asm volatile("mma.sync.aligned.m16n8k16.row.col.f32.f16.f16.f32 "
                 "{%0,%1,%2,%3}, {%4,%5,%6,%7}, {%8,%9}, {%0,%1,%2,%3};"
                 : "+f"(d[0]), "+f"(d[1]), "+f"(d[2]), "+f"(d[3])
                 : "r"(a[0]), "r"(a[1]), "r"(a[2]), "r"(a[3]), "r"(b[0]), "r"(b[1]));
}

// ---------------------------------------------------------------------------
// Kernel 0: prep — conv_w -> fp16 pitched tile, fold bn2.
// ---------------------------------------------------------------------------
__global__ __launch_bounds__(256) void prep_kernel(
    const float* __restrict__ convw,   // (O, G) row-major
    const float* __restrict__ bn2_g, const float* __restrict__ bn2_b,
    const float* __restrict__ bn2_m, const float* __restrict__ bn2_v)
{
    const int i = blockIdx.x * 256 + threadIdx.x;   // 0..16383
    const int k = i & 63;
    const int o = i >> 6;
    g_Whalf[o * WPITCH + k] = __float2half(convw[o * GG + k]);
    if (i < OO) {
        // zero the pad region (never read by ldmatrix, but keep deterministic)
        g_Whalf[i * WPITCH + 64] = __float2half(0.f);
        g_Whalf[i * WPITCH + 65] = __float2half(0.f);
        g_Whalf[i * WPITCH + 66] = __float2half(0.f);
        g_Whalf[i * WPITCH + 67] = __float2half(0.f);
        g_Whalf[i * WPITCH + 68] = __float2half(0.f);
        g_Whalf[i * WPITCH + 69] = __float2half(0.f);
        g_Whalf[i * WPITCH + 70] = __float2half(0.f);
        g_Whalf[i * WPITCH + 71] = __float2half(0.f);
        float sc = bn2_g[i] * rsqrtf(bn2_v[i] + 1e-5f);
        float bi = bn2_b[i] - sc * bn2_m[i];
        g_bn2[i] = make_float2(sc, bi);
    }
}

// ---------------------------------------------------------------------------
// Kernel 1: attention statistics (HBM-bound, ~62us). Unchanged.
// ---------------------------------------------------------------------------
__global__ __launch_bounds__(256) void attn_kernel(
    const float* __restrict__ x,
    const float* __restrict__ aw,
    const float* __restrict__ bn1_g, const float* __restrict__ bn1_b,
    const float* __restrict__ bn1_m, const float* __restrict__ bn1_v)
{
    const int bg = blockIdx.x;
    const int g  = bg & 63;
    const float* xb = x + (size_t)bg * 3 * HWN;

    const int t    = threadIdx.x;
    const int lane = t & 31;
    const int warp = t >> 5;

    float acc[9];
#pragma unroll
    for (int q = 0; q < 9; q++) acc[q] = 0.0f;

#pragma unroll 1
    for (int it = 0; it < 16; it++) {
        const int wIdx = it * 256 + t;
        const int wy = wIdx >> 6;
        const int wx = wIdx & 63;
        float m[3], s[3];
#pragma unroll
        for (int ch = 0; ch < 3; ch++) {
            const float4* pc = (const float4*)(xb + (size_t)ch * HWN + (wy * 4) * 256 + wx * 4);
            float4 r0 = __ldcs(pc);
            float4 r1 = __ldcs(pc + 64);
            float4 r2 = __ldcs(pc + 128);
            float4 r3 = __ldcs(pc + 192);
            float mx = fmaxf(fmaxf(fmaxf(r0.x, r0.y), fmaxf(r0.z, r0.w)),
                      fmaxf(fmaxf(fmaxf(r1.x, r1.y), fmaxf(r1.z, r1.w)),
                      fmaxf(fmaxf(fmaxf(r2.x, r2.y), fmaxf(r2.z, r2.w)),
                            fmaxf(fmaxf(r3.x, r3.y), fmaxf(r3.z, r3.w)))));
            float sm = (r0.x + r0.y + r0.z + r0.w) + (r1.x + r1.y + r1.z + r1.w)
                     + (r2.x + r2.y + r2.z + r2.w) + (r3.x + r3.y + r3.z + r3.w);
            m[ch] = mx;
            s[ch] = sm;
        }
#pragma unroll
        for (int i = 0; i < 3; i++)
#pragma unroll
            for (int j = 0; j < 3; j++)
                acc[i * 3 + j] += m[i] * s[j];
    }

    __shared__ float red[9][8];
    __shared__ float fin[9];
#pragma unroll
    for (int q = 0; q < 9; q++) {
        float v = acc[q];
#pragma unroll
        for (int off = 16; off > 0; off >>= 1)
            v += __shfl_xor_sync(0xFFFFFFFFu, v, off);
        if (lane == 0) red[q][warp] = v;
    }
    __syncthreads();
    if (t < 9) {
        float s = 0.0f;
#pragma unroll
        for (int w = 0; w < 8; w++) s += red[t][w];
        fin[t] = s;
    }
    __syncthreads();

    if (t == 0) {
        const float w0 = aw[g * 3 + 0], w1 = aw[g * 3 + 1], w2 = aw[g * 3 + 2];
        float r0 = (fin[0] * w0 + fin[3] * w1 + fin[6] * w2) * (1.0f / 1024.0f);
        float r1 = (fin[1] * w0 + fin[4] * w1 + fin[7] * w2) * (1.0f / 1024.0f);
        float r2 = (fin[2] * w0 + fin[5] * w1 + fin[8] * w2) * (1.0f / 1024.0f);
        float mx = fmaxf(r0, fmaxf(r1, r2));
        float e0 = __expf(r0 - mx), e1 = __expf(r1 - mx), e2 = __expf(r2 - mx);
        float inv = 1.0f / (e0 + e1 + e2);
        float sc = bn1_g[g] * rsqrtf(bn1_v[g] + 1e-5f);
        float cc = bn1_b[g] - sc * bn1_m[g];
        float4 o;
        o.x = sc * e0 * inv;
        o.y = sc * e1 * inv;
        o.z = sc * e2 * inv;
        o.w = cc;
        g_attnW[bg] = o;
    }
}

// ---------------------------------------------------------------------------
// Kernel 2: fused weighted-sum + bn1 + relu + 1x1 conv via mma.sync fp16 + bn2.
// CTA: 256 threads (8 warps), 2 CTAs/SM. Tile: 256 o x 64 n, K = 64.
// Phase A: Y[n][k] fp16 in smem (pitch 72). Phase B: warp = 64o x 32n,
// m16n8k16 HMMA, fp32 accumulate. Epilogue: bn2 fold, float2 stores.
// ---------------------------------------------------------------------------
__global__ __launch_bounds__(256, 2) void fused_kernel(
    const float* __restrict__ x,
    float* __restrict__ out)
{
    __shared__ __align__(16) __half Wsm[OO * WPITCH];   // 36864 B
    __shared__ __align__(16) __half Ysm[64 * WPITCH];   //  9216 B

    const int t    = threadIdx.x;
    const int lane = t & 31;
    const int wid  = t >> 5;
    const int b    = blockIdx.y;
    const int n0   = blockIdx.x * 64;

    // ---- W copy to smem (36864 B = 2304 float4) ----
    {
        const float4* src = (const float4*)g_Whalf;
        float4* dst = (float4*)Wsm;
#pragma unroll
        for (int i = 0; i < 9; i++)
            dst[i * 256 + t] = __ldg(src + i * 256 + t);
    }

    // ---- Phase A: Y = relu(bn1(sum_j a_j x_j)) -> fp16 smem [n][k] ----
    {
        const int pos = t & 63;
        const int gq  = t >> 6;                       // 0..3
        const float* xb = x + (size_t)b * CC * HWN + n0 + pos;
        const float4* awb = g_attnW + b * GG;
        __half* yrow = Ysm + pos * WPITCH;
#pragma unroll
        for (int it = 0; it < 16; it++) {
            const int g = it * 4 + gq;
            const float4 a = __ldg(awb + g);
            const float* p = xb + (size_t)(g * 3) * HWN;
            float x0 = __ldcs(p);
            float x1 = __ldcs(p + HWN);
            float x2 = __ldcs(p + 2 * HWN);
            float y = fmaf(a.x, x0, fmaf(a.y, x1, fmaf(a.z, x2, a.w)));
            yrow[g] = __float2half(fmaxf(y, 0.0f));
        }
    }
    __syncthreads();

    // ---- Phase B: HMMA GEMM. warp tile: o in [ow, ow+64), n in [nw, nw+32) ----
    const int ow = (wid >> 1) * 64;
    const int nw = (wid & 1) * 32;

    float acc[4][4][4];
#pragma unroll
    for (int m = 0; m < 4; m++)
#pragma unroll
        for (int j = 0; j < 4; j++)
#pragma unroll
            for (int q = 0; q < 4; q++) acc[m][j][q] = 0.0f;

    // ldmatrix base addresses
    const uint32_t wbase = smem_u32(Wsm);
    const uint32_t ybase = smem_u32(Ysm);
    // A: row = ow + m*16 + (lane&15), col byte = ((lane>>4)*8 + k0)*2
    const uint32_t aAddr = wbase + (ow + (lane & 15)) * (WPITCH * 2) + ((lane >> 4) * 8) * 2;
    // B: row = nw + j*8 + (lane&7), col byte = (((lane>>3)&1)*8 + k0)*2
    const uint32_t bAddr = ybase + (nw + (lane & 7)) * (WPITCH * 2) + (((lane >> 3) & 1) * 8) * 2;

#pragma unroll
    for (int k0 = 0; k0 < 64; k0 += 16) {
        uint32_t afr[4][4];
#pragma unroll
        for (int m = 0; m < 4; m++)
            ldmat_x4(afr[m], aAddr + m * 16 * (WPITCH * 2) + k0 * 2);
        uint32_t bfr[4][2];
#pragma unroll
        for (int j = 0; j < 4; j++)
            ldmat_x2(bfr[j], bAddr + j * 8 * (WPITCH * 2) + k0 * 2);
#pragma unroll
        for (int m = 0; m < 4; m++)
#pragma unroll
            for (int j = 0; j < 4; j++)
                mma_16816(acc[m][j], afr[m], bfr[j]);
    }

    // ---- Epilogue: bn2 + store ----
    // acc[m][j]: d0,d1 -> row ow+m*16+(lane>>2), cols nw+j*8+(lane&3)*2 (+1)
    //            d2,d3 -> row +8
    {
        const int ncol = n0 + nw + (lane & 3) * 2;
#pragma unroll
        for (int m = 0; m < 4; m++) {
            const int r0 = ow + m * 16 + (lane >> 2);
            const int r1 = r0 + 8;
            const float2 s0 = __ldg(&g_bn2[r0]);
            const float2 s1 = __ldg(&g_bn2[r1]);
            float* p0 = out + ((size_t)(b * OO + r0)) * HWN + ncol;
            float* p1 = out + ((size_t)(b * OO + r1)) * HWN + ncol;
#pragma unroll
            for (int j = 0; j < 4; j++) {
                float2 v0, v1;
                v0.x = fmaf(acc[m][j][0], s0.x, s0.y);
                v0.y = fmaf(acc[m][j][1], s0.x, s0.y);
                v1.x = fmaf(acc[m][j][2], s1.x, s1.y);
                v1.y = fmaf(acc[m][j][3], s1.x, s1.y);
                *(float2*)(p0 + j * 8) = v0;
                *(float2*)(p1 + j * 8) = v1;
            }
        }
    }
}

extern "C" void kernel_launch(void* const* d_in, const int* in_sizes, int n_in,
                              void* d_out, int out_size)
{
    const float* x     = (const float*)d_in[0];
    const float* aw    = (const float*)d_in[1];
    const float* bn1_g = (const float*)d_in[2];
    const float* bn1_b = (const float*)d_in[3];
    const float* bn1_m = (const float*)d_in[4];
    const float* bn1_v = (const float*)d_in[5];
    const float* convw = (const float*)d_in[6];
    const float* bn2_g = (const float*)d_in[7];
    const float* bn2_b = (const float*)d_in[8];
    const float* bn2_m = (const float*)d_in[9];
    const float* bn2_v = (const float*)d_in[10];
    float* out = (float*)d_out;

    prep_kernel<<<64, 256>>>(convw, bn2_g, bn2_b, bn2_m, bn2_v);
    attn_kernel<<<BB * GG, 256>>>(x, aw, bn1_g, bn1_b, bn1_m, bn1_v);
    fused_kernel<<<dim3(HWN / 64, BB), 256>>>(x, out);
}